// round 16
// baseline (speedup 1.0000x reference)
#include <cuda_runtime.h>
#include <math.h>

// LFQ: x [2,128,20] fp32 -> 256 tokens, D=20, K=2^20, TEMP=0.005.
// Out: q (5120 floats = sign(x)) then entro_mean, mean_entro, entro_loss,
// commit_loss.
//
// prob(code c|t) = e^{-r_t} * exp(-pen); pen = sum of w_d = 400|x_d| over
// dims flipped vs the hard sign code. Flips of dims with w_d >= 45 underflow
// to 0 in fp32 (same underflow as the reference's own softmax), so survivor
// masks are subsets of the soft-dim set {d : w_d < 45} (~1 per half).
//
// R16 latency surgery over R15 (warp-per-token, subset enumeration, CAS
// epoch-table with telescoping entropy):
//  - slot PREFETCH (__ldcg) issued right after enumeration; the MUFU-heavy
//    stats chain runs under its shadow, so the CAS sees a warm guess.
//  - split finalize: ticket-1 after stats publishes entro_mean + commit_loss
//    (overlapped with scatter); ticket-2 tail is just accS/accH loads + 2
//    stores. Epoch bump replaces table repair across graph replays.

#define TOK    256
#define DIMS   20
#define THRESH 45.0f            // exp(-45)=2.9e-20, below fp32 softmax noise
#define MCAP   (1 << 20)
#define CAP    64               // survivor cap per half (unreachable bound)
#define FULLM  0xFFFFFFFFu

__device__ unsigned long long g_T[MCAP];  // {epoch:u32, val:f32}; zero at load
__device__ unsigned g_epoch = 1u;         // current-launch tag (tag 0 = clean)
__device__ unsigned g_t1;                 // stats ticket; reset each run
__device__ unsigned g_t2;                 // scatter ticket; reset each run
__device__ double   g_accH;               // sum of per-token entropies
__device__ double   g_accC;               // sum of commit partials
__device__ double   g_accS;               // mean_probs entropy sum

__device__ __forceinline__ float entf(float v) {
    // f(v) = -(v/256)*log(v/256 + 1e-10); f(0) = 0
    float m = v * (1.0f / 256.0f);
    return (m > 0.f) ? -m * __logf(m + 1e-10f) : 0.f;
}

__global__ void __launch_bounds__(256, 4)
k_lfq(const float* __restrict__ x, float* __restrict__ outq,
      float* __restrict__ out4) {
    __shared__ int   sCA[8][CAP]; __shared__ float sVA[8][CAP];
    __shared__ int   sCB[8][CAP]; __shared__ float sVB[8][CAP];
    __shared__ int   s_nA[8], s_nB[8];

    const int tid  = threadIdx.x;
    const int w    = tid >> 5;               // warp = token within block
    const int lane = tid & 31;
    const int t    = blockIdx.x * 8 + w;

    if (lane == 0) { s_nA[w] = 0; s_nB[w] = 0; }

    // input load first; epoch load overlaps (broadcast)
    float xv = (lane < DIMS) ? x[t * DIMS + lane] : 0.f;
    const unsigned ep = g_epoch;

    float sg = (xv > 0.f) ? 1.f : -1.f;
    float wv = (lane < DIMS) ? 400.0f * fabsf(xv) : 1e30f;
    if (lane < DIMS) outq[t * DIMS + lane] = sg;     // fire-and-forget

    unsigned bal = __ballot_sync(FULLM, (lane < DIMS) && (xv > 0.f));
    const unsigned hhi = bal & 0x3FFu;               // hard bits, dims 0..9
    const unsigned hlo = (bal >> 10) & 0x3FFu;       // hard bits, dims 10..19
    unsigned sb  = __ballot_sync(FULLM, wv < THRESH);
    const unsigned Shi = sb & 0x3FFu;                // soft sets
    const unsigned Slo = (sb >> 10) & 0x3FFu;

    // ---- enumeration FIRST (cheap ALU) so slot indices exist early ----
    #pragma unroll
    for (int half = 0; half < 2; half++) {
        const unsigned S  = half ? Slo : Shi;
        const unsigned hc = half ? hlo : hhi;
        const int dbase   = half ? 10 : 0;
        const int nsub    = 1 << __popc(S);          // warp-uniform
        for (int base = 0; base < nsub; base += 32) {
            int sub = base + lane;
            unsigned s = S, mask = 0;
            float pen = 0.f;
            int bit = 0;
            while (s) {                              // warp-uniform trips
                int d = __ffs(s) - 1; s &= s - 1;
                float wd = __shfl_sync(FULLM, wv, d + dbase);
                if ((sub >> bit) & 1) { pen += wd; mask |= 1u << d; }
                bit++;
            }
            if (sub < nsub && pen < THRESH) {
                if (half == 0) {
                    int p = atomicAdd(&s_nA[w], 1);
                    if (p < CAP) { sCA[w][p] = (int)(hhi ^ mask); sVA[w][p] = __expf(-pen); }
                } else {
                    int p = atomicAdd(&s_nB[w], 1);
                    if (p < CAP) { sCB[w][p] = (int)(hc ^ mask); sVB[w][p] = __expf(-pen); }
                }
            }
        }
    }
    __syncwarp();

    const int na = min(s_nA[w], CAP), nb = min(s_nB[w], CAP);
    const int total = na * nb;

    // ---- prefetch this lane's first slot (hidden under stats below) ----
    unsigned long long* slot0 = 0;
    unsigned long long  cur0  = 0;
    float vv0 = 0.f;
    if (lane < total) {
        int i = lane / nb, j = lane - i * nb;
        vv0 = sVA[w][i] * sVB[w][j];
        if (vv0 > 0.f) {
            slot0 = &g_T[sCA[w][i] * 1024 + sCB[w][j]];
            cur0  = __ldcg(slot0);
        }
    }

    // ---- stats under the prefetch shadow: H, commit, e^{-r} ----
    float e  = __expf(-wv);                          // lanes>=20: e=0
    float rp = __logf(1.0f + e);                     //            rp=0
    float Hp = rp + wv * e / (1.0f + e);             //            Hp=0
    float cp = (lane < DIMS) ? (xv - sg) * (xv - sg) : 0.f;
    float pr = 1.0f / (1.0f + e);                    //            pr=1
    #pragma unroll
    for (int o = 16; o > 0; o >>= 1) {
        Hp += __shfl_down_sync(FULLM, Hp, o);
        cp += __shfl_down_sync(FULLM, cp, o);
        pr *= __shfl_down_sync(FULLM, pr, o);
    }
    const float er = __shfl_sync(FULLM, pr, 0);      // e^{-r_t}
    if (lane == 0) {
        atomicAdd(&g_accH, (double)Hp);              // REDG.64, no return
        atomicAdd(&g_accC, (double)cp);
        __threadfence();                             // release partials
        unsigned tk = atomicAdd(&g_t1, 1u);
        if (tk == TOK - 1u) {                        // early finalize, runs
            __threadfence();                         // concurrent w/ scatter
            double vh = *(volatile double*)&g_accH;
            double vc = *(volatile double*)&g_accC;
            out4[0] = (float)(vh * (1.0 / 256.0));   // entro_mean_s
            out4[3] = (float)(vc * (1.0 / 5120.0));  // commit_loss
        }
    }

    // ---- CAS scatter with telescoping entropy (prefetched first item) ----
    float ds = 0.f;
    if (slot0) {
        float v = er * vv0;
        unsigned long long cur = cur0;
        for (;;) {
            float oldv = ((unsigned)(cur >> 32) == ep)
                           ? __uint_as_float((unsigned)cur) : 0.f;
            float newv = oldv + v;
            unsigned long long des =
                ((unsigned long long)ep << 32) | __float_as_uint(newv);
            unsigned long long prev = atomicCAS(slot0, cur, des);
            if (prev == cur) { ds += entf(newv) - entf(oldv); break; }
            cur = prev;                              // collision: retry
        }
    }
    for (int k = lane + 32; k < total; k += 32) {    // rare residual
        int i = k / nb, j = k - i * nb;
        float v = er * sVA[w][i] * sVB[w][j];
        if (v > 0.f) {
            unsigned long long* slot = &g_T[sCA[w][i] * 1024 + sCB[w][j]];
            unsigned long long cur = __ldcg(slot);
            for (;;) {
                float oldv = ((unsigned)(cur >> 32) == ep)
                               ? __uint_as_float((unsigned)cur) : 0.f;
                float newv = oldv + v;
                unsigned long long des =
                    ((unsigned long long)ep << 32) | __float_as_uint(newv);
                unsigned long long prev = atomicCAS(slot, cur, des);
                if (prev == cur) { ds += entf(newv) - entf(oldv); break; }
                cur = prev;
            }
        }
    }

    // ---- warp-reduce ds; ticket-2 tail: 2 loads + 2 stores + resets ----
    #pragma unroll
    for (int o = 16; o > 0; o >>= 1)
        ds += __shfl_down_sync(FULLM, ds, o);
    if (lane == 0) {
        atomicAdd(&g_accS, (double)ds);
        __threadfence();                             // release partials
        unsigned tk = atomicAdd(&g_t2, 1u);
        if (tk == TOK - 1u) {                        // 256 warps total
            __threadfence();                         // acquire all partials
            double vs = *(volatile double*)&g_accS;  // two independent loads
            double vh = *(volatile double*)&g_accH;  // issue back-to-back
            double em = vh * (1.0 / 256.0);
            out4[1] = (float)vs;                     // mean_entro
            out4[2] = (float)(em - vs);              // entro_loss (ALPHA=1)
            g_t1 = 0u; g_t2 = 0u;                    // reset for replay
            g_accH = 0.0; g_accC = 0.0; g_accS = 0.0;
            g_epoch = ep + 1u;                       // invalidate table
        }
    }
}

extern "C" void kernel_launch(void* const* d_in, const int* in_sizes, int n_in,
                              void* d_out, int out_size) {
    const float* x = (const float*)d_in[0];
    float* out = (float*)d_out;
    int qn = in_sizes[0];                            // 5120

    k_lfq<<<32, 256>>>(x, out, out + qn);
}